// round 12
// baseline (speedup 1.0000x reference)
#include <cuda_runtime.h>
#include <cuda_bf16.h>
#include <math.h>
#include <stdint.h>

// ---------------- problem-size maxima ----------------
#define MAXN   50000
#define MAXE   400000
#define MAXET  (MAXE + MAXN)
#define MAXHC  512
#define MAXM   256

// ---------------- device scratch ----------------
__device__ int   g_src [MAXET];
__device__ int   g_dst [MAXET];
__device__ int   g_srcs[MAXET];
__device__ int   g_cnt [MAXN];
__device__ int   g_rp  [MAXN + 1];
__device__ int   g_cur [MAXN];
__device__ int   g_is64;

__device__ float g_h1 [(size_t)MAXN * MAXHC];
__device__ float g_h2 [(size_t)MAXN * MAXM];
__device__ float g_hd [(size_t)MAXN * MAXM];
__device__ __nv_bfloat16 g_ahi[(size_t)MAXN * MAXHC];
__device__ __nv_bfloat16 g_alo[(size_t)MAXN * MAXHC];
__device__ __nv_bfloat16 g_wthi[512 * 512];
__device__ __nv_bfloat16 g_wtlo[512 * 512];
__device__ float g_as1[(size_t)MAXN * 4], g_ad1[(size_t)MAXN * 4];
__device__ float g_as2[MAXN], g_ad2[MAXN];
__device__ float g_asd[MAXN], g_add[MAXN];

// ---------------- PTX helpers ----------------
__device__ __forceinline__ uint32_t smem_u32(const void* p) {
    uint32_t a;
    asm("{ .reg .u64 t; cvta.to.shared.u64 t, %1; cvt.u32.u64 %0, t; }" : "=r"(a) : "l"(p));
    return a;
}
__device__ __forceinline__ void ldmx4(uint32_t* r, uint32_t addr) {
    asm volatile("ldmatrix.sync.aligned.m8n8.x4.shared.b16 {%0,%1,%2,%3}, [%4];"
        : "=r"(r[0]), "=r"(r[1]), "=r"(r[2]), "=r"(r[3]) : "r"(addr));
}
__device__ __forceinline__ void mma16816(float* c, const uint32_t* a,
                                         uint32_t b0, uint32_t b1) {
    asm volatile(
        "mma.sync.aligned.m16n8k16.row.col.f32.bf16.bf16.f32 "
        "{%0,%1,%2,%3}, {%4,%5,%6,%7}, {%8,%9}, {%0,%1,%2,%3};"
        : "+f"(c[0]), "+f"(c[1]), "+f"(c[2]), "+f"(c[3])
        : "r"(a[0]), "r"(a[1]), "r"(a[2]), "r"(a[3]), "r"(b0), "r"(b1));
}
__device__ __forceinline__ void cpa16(uint32_t dst, const void* src, uint32_t sz) {
    asm volatile("cp.async.cg.shared.global [%0], [%1], 16, %2;"
                 :: "r"(dst), "l"(src), "r"(sz) : "memory");
}
#define CP_COMMIT() asm volatile("cp.async.commit_group;" ::: "memory")
#define CP_WAIT0()  asm volatile("cp.async.wait_group 0;" ::: "memory")
#define CP_WAIT2()  asm volatile("cp.async.wait_group 2;" ::: "memory")

// ---------------- graph-building kernels ----------------
__global__ void detect_kernel(const int* __restrict__ ei32, int E) {
    if (threadIdx.x == 0 && blockIdx.x == 0) {
        int nz = 0;
        int cnt = E < 64 ? E : 64;
        for (int i = 0; i < cnt; i++) nz |= ei32[2 * i + 1];
        g_is64 = (nz == 0) ? 1 : 0;
    }
}
__global__ void build_edges(const void* __restrict__ ei, int E, int Nn) {
    int i = blockIdx.x * blockDim.x + threadIdx.x;
    int tot = E + Nn;
    if (i >= tot) return;
    int s, d;
    if (i < E) {
        if (g_is64) {
            const long long* p = (const long long*)ei;
            s = (int)p[i]; d = (int)p[E + i];
        } else {
            const int* p = (const int*)ei;
            s = p[i]; d = p[E + i];
        }
    } else { s = d = i - E; }
    g_src[i] = s; g_dst[i] = d;
}
__global__ void zero_int(int* p, int n) {
    int i = blockIdx.x * blockDim.x + threadIdx.x;
    if (i < n) p[i] = 0;
}
__global__ void hist_kernel(int tot) {
    int i = blockIdx.x * blockDim.x + threadIdx.x;
    if (i < tot) atomicAdd(&g_cnt[g_dst[i]], 1);
}
__global__ void scan_kernel(int n) {
    __shared__ int sh[1024];
    __shared__ int carry;
    if (threadIdx.x == 0) carry = 0;
    __syncthreads();
    for (int base = 0; base < n; base += 1024) {
        int i = base + threadIdx.x;
        int v = (i < n) ? g_cnt[i] : 0;
        sh[threadIdx.x] = v;
        __syncthreads();
        for (int off = 1; off < 1024; off <<= 1) {
            int t = (threadIdx.x >= off) ? sh[threadIdx.x - off] : 0;
            __syncthreads();
            sh[threadIdx.x] += t;
            __syncthreads();
        }
        if (i < n) g_rp[i + 1] = sh[threadIdx.x] + carry;
        __syncthreads();
        if (threadIdx.x == 0) carry += sh[1023];
        __syncthreads();
    }
    if (threadIdx.x == 0) g_rp[0] = 0;
}
__global__ void copy_cursor(int n) {
    int i = blockIdx.x * blockDim.x + threadIdx.x;
    if (i < n) g_cur[i] = g_rp[i];
}
__global__ void scatter_kernel(int tot) {
    int i = blockIdx.x * blockDim.x + threadIdx.x;
    if (i >= tot) return;
    int d = g_dst[i];
    int pos = atomicAdd(&g_cur[d], 1);
    g_srcs[pos] = g_src[i];
}

// ---------------- bf16 split conversions ----------------
__global__ void split_kernel(const float* __restrict__ src,
                             __nv_bfloat16* __restrict__ hi,
                             __nv_bfloat16* __restrict__ lo, int total) {
    int i = blockIdx.x * blockDim.x + threadIdx.x;
    if (i >= total) return;
    float v = src[i];
    __nv_bfloat16 h = __float2bfloat16(v);
    hi[i] = h;
    lo[i] = __float2bfloat16(v - __bfloat162float(h));
}
__global__ void wtsplit_kernel(const float* __restrict__ W,
                               __nv_bfloat16* __restrict__ hi,
                               __nv_bfloat16* __restrict__ lo, int K, int N) {
    int idx = blockIdx.x * blockDim.x + threadIdx.x;
    if (idx >= K * N) return;
    int k = idx / N, n = idx - k * N;
    float v = W[idx];
    __nv_bfloat16 h = __float2bfloat16(v);
    hi[(size_t)n * K + k] = h;
    lo[(size_t)n * K + k] = __float2bfloat16(v - __bfloat162float(h));
}

// ---------------- split-bf16 tensor-core GEMM, 4-stage cp.async pipeline -----
// C[M,N] = Ahi/lo[M,K] @ (Bt hi/lo[N,K])^T, fp32 accumulate.
// CTA tile 128x128, BK=16, 8 warps (4M x 2N), warp tile 32x64.
// Packed 32B-pitch smem with XOR-16B swizzle (conflict-free, 16B-aligned).
// K%16==0 (and K/16 >= 4), N%128==0, M guarded.
#define PITCH  32
#define TILEB  (128 * PITCH)           // 4 KB
#define STAGES 4
#define G_SMEM (STAGES * 4 * TILEB)    // 64 KB
__device__ __forceinline__ uint32_t swz(uint32_t row, uint32_t u) {
    return row * PITCH + ((u ^ ((row >> 2) & 1u)) << 4);
}
__global__ void __launch_bounds__(256, 2)
mma_gemm(const __nv_bfloat16* __restrict__ Ahi, const __nv_bfloat16* __restrict__ Alo,
         const __nv_bfloat16* __restrict__ Bhi, const __nv_bfloat16* __restrict__ Blo,
         float* __restrict__ C, int M, int K, int N) {
    extern __shared__ __align__(16) uint8_t smem[];   // [stage][op][TILEB]
    int tid = threadIdx.x, lane = tid & 31, wid = tid >> 5;
    int wm = wid & 3, wn = wid >> 2;
    int m0 = blockIdx.y * 128, n0 = blockIdx.x * 128;
    uint32_t sbase = smem_u32(smem);

    // cp.async mapping: thread t -> row r = t>>1, 16B half hb = t&1
    int r = tid >> 1, hb = tid & 1;
    int gmA = m0 + r;
    const size_t aoff = (size_t)gmA * K + hb * 8;
    const size_t boff = (size_t)(n0 + r) * K + hb * 8;
    uint32_t soff = swz((uint32_t)r, (uint32_t)hb);
    uint32_t szA = (gmA < M) ? 16u : 0u;

    // ldmatrix fragment offsets (swizzled)
    uint32_t aoffs[2], boffs[4];
#pragma unroll
    for (int mt = 0; mt < 2; mt++) {
        uint32_t row = (uint32_t)(wm * 32 + mt * 16 + (lane & 15));
        aoffs[mt] = swz(row, (uint32_t)(lane >> 4));
    }
#pragma unroll
    for (int p = 0; p < 4; p++) {
        uint32_t row = (uint32_t)(wn * 64 + p * 16 + (lane & 15));
        boffs[p] = swz(row, (uint32_t)(lane >> 4));
    }

    float acc[2][8][4];
#pragma unroll
    for (int i = 0; i < 2; i++)
#pragma unroll
        for (int j = 0; j < 8; j++)
#pragma unroll
            for (int q = 0; q < 4; q++) acc[i][j][q] = 0.f;

#define LOAD_CHUNK(k0, b)                                                    \
    do {                                                                     \
        uint32_t bb_ = sbase + (uint32_t)(b) * 4 * TILEB + soff;             \
        cpa16(bb_,             Ahi + aoff + (k0), szA);                      \
        cpa16(bb_ + TILEB,     Alo + aoff + (k0), szA);                      \
        cpa16(bb_ + 2 * TILEB, Bhi + boff + (k0), 16u);                      \
        cpa16(bb_ + 3 * TILEB, Blo + boff + (k0), 16u);                      \
    } while (0)

    int nch = K >> 4;
    // prologue: stages 0..STAGES-2
#pragma unroll
    for (int s = 0; s < STAGES - 1; s++) {
        LOAD_CHUNK(s * 16, s);
        CP_COMMIT();
    }
    CP_WAIT2();          // chunk 0 complete
    __syncthreads();

    for (int ch = 0; ch < nch; ch++) {
        int nxt = ch + STAGES - 1;
        if (nxt < nch) {
            LOAD_CHUNK(nxt * 16, nxt & (STAGES - 1));
            CP_COMMIT();
        }
        uint32_t tb = sbase + (uint32_t)(ch & (STAGES - 1)) * 4 * TILEB;
        uint32_t AH[2][4], AL[2][4];
        ldmx4(AH[0], tb + aoffs[0]);
        ldmx4(AH[1], tb + aoffs[1]);
        ldmx4(AL[0], tb + TILEB + aoffs[0]);
        ldmx4(AL[1], tb + TILEB + aoffs[1]);
#pragma unroll
        for (int p = 0; p < 4; p++) {
            uint32_t BH[4], BL[4];
            ldmx4(BH, tb + 2 * TILEB + boffs[p]);
            ldmx4(BL, tb + 3 * TILEB + boffs[p]);
#pragma unroll
            for (int mt = 0; mt < 2; mt++) {
                mma16816(acc[mt][p * 2 + 0], AH[mt], BH[0], BH[2]);
                mma16816(acc[mt][p * 2 + 1], AH[mt], BH[1], BH[3]);
                mma16816(acc[mt][p * 2 + 0], AH[mt], BL[0], BL[2]);
                mma16816(acc[mt][p * 2 + 1], AH[mt], BL[1], BL[3]);
                mma16816(acc[mt][p * 2 + 0], AL[mt], BH[0], BH[2]);
                mma16816(acc[mt][p * 2 + 1], AL[mt], BH[1], BH[3]);
            }
        }
        if (ch + 1 < nch) {
            if (nxt < nch) CP_WAIT2(); else CP_WAIT0();
            __syncthreads();
        }
    }
#undef LOAD_CHUNK

#pragma unroll
    for (int mt = 0; mt < 2; mt++) {
        int gr0 = m0 + wm * 32 + mt * 16 + (lane >> 2);
        int gr1 = gr0 + 8;
#pragma unroll
        for (int nt = 0; nt < 8; nt++) {
            int gc = n0 + wn * 64 + nt * 8 + (lane & 3) * 2;
            if (gr0 < M)
                *(float2*)(C + (size_t)gr0 * N + gc) = make_float2(acc[mt][nt][0], acc[mt][nt][1]);
            if (gr1 < M)
                *(float2*)(C + (size_t)gr1 * N + gc) = make_float2(acc[mt][nt][2], acc[mt][nt][3]);
        }
    }
}

// ---------------- per-node attention logits ----------------
__global__ void alpha_kernel(const float* __restrict__ feat,
                             const float* __restrict__ a_src,
                             const float* __restrict__ a_dst,
                             float* __restrict__ as_, float* __restrict__ ad_,
                             int Nn, int H, int C) {
    int warp = (blockIdx.x * blockDim.x + threadIdx.x) >> 5;
    int lane = threadIdx.x & 31;
    if (warp >= Nn * H) return;
    int n = warp / H, h = warp - n * H;
    const float* f = feat + (size_t)n * H * C + h * C;
    const float* s = a_src + h * C;
    const float* d = a_dst + h * C;
    float ss = 0.f, dd = 0.f;
    for (int c = lane; c < C; c += 32) {
        float v = f[c];
        ss = fmaf(v, s[c], ss);
        dd = fmaf(v, d[c], dd);
    }
#pragma unroll
    for (int o = 16; o; o >>= 1) {
        ss += __shfl_down_sync(0xffffffffu, ss, o);
        dd += __shfl_down_sync(0xffffffffu, dd, o);
    }
    if (lane == 0) { as_[warp] = ss; ad_[warp] = dd; }
}

// ---------------- GAT segment-softmax + aggregate (float4 channels) ----------
// blockDim = H*C/4; each thread owns 4 consecutive channels.
#define CHUNK 64
__global__ void gat_aggregate(const float* __restrict__ feat,
                              const float* __restrict__ as_,
                              const float* __restrict__ ad_,
                              const float* __restrict__ bias,
                              float* __restrict__ out,            // nullable
                              __nv_bfloat16* __restrict__ ohi,    // nullable
                              __nv_bfloat16* __restrict__ olo,
                              int H, int C, int prelu,
                              const float* __restrict__ prelu_a) {
    int n = blockIdx.x;
    int t = threadIdx.x;
    int HC = H * C;
    int t4 = t * 4;
    int h = t4 / C;
    __shared__ float sw[4 * CHUNK];
    __shared__ int   ssrc[CHUNK];
    int s0 = g_rp[n], s1 = g_rp[n + 1];
    int warp = t >> 5, lane = t & 31;

    // phase 1: softmax stats in head-warp registers
    float m = 0.f, rdn = 0.f, ad = 0.f;
    if (warp < H) {
        ad = ad_[(size_t)n * H + warp];
        m = -INFINITY;
        for (int k = s0 + lane; k < s1; k += 32) {
            float e = as_[(size_t)g_srcs[k] * H + warp] + ad;
            e = e > 0.f ? e : 0.2f * e;
            m = fmaxf(m, e);
        }
#pragma unroll
        for (int o = 16; o; o >>= 1) m = fmaxf(m, __shfl_xor_sync(0xffffffffu, m, o));
        float ds = 0.f;
        for (int k = s0 + lane; k < s1; k += 32) {
            float e = as_[(size_t)g_srcs[k] * H + warp] + ad;
            e = e > 0.f ? e : 0.2f * e;
            ds += __expf(e - m);
        }
#pragma unroll
        for (int o = 16; o; o >>= 1) ds += __shfl_xor_sync(0xffffffffu, ds, o);
        rdn = 1.f / (ds + 1e-16f);
    }

    // phase 2: chunked weights + float4 gather/accumulate
    float4 acc = make_float4(0.f, 0.f, 0.f, 0.f);
    for (int base = s0; base < s1; base += CHUNK) {
        int count = min(CHUNK, s1 - base);
        __syncthreads();
        if (warp < H) {
            for (int j = lane; j < count; j += 32) {
                int s = g_srcs[base + j];
                if (warp == 0) ssrc[j] = s;
                float e = as_[(size_t)s * H + warp] + ad;
                e = e > 0.f ? e : 0.2f * e;
                sw[warp * CHUNK + j] = __expf(e - m) * rdn;
            }
        }
        __syncthreads();
        const float* swh = sw + h * CHUNK;
        for (int j = 0; j < count; j++) {
            float4 f = *(const float4*)(feat + (size_t)ssrc[j] * HC + t4);
            float w = swh[j];
            acc.x = fmaf(f.x, w, acc.x);
            acc.y = fmaf(f.y, w, acc.y);
            acc.z = fmaf(f.z, w, acc.z);
            acc.w = fmaf(f.w, w, acc.w);
        }
    }

    float4 b4 = *(const float4*)(bias + t4);
    float v0 = acc.x + b4.x, v1 = acc.y + b4.y, v2 = acc.z + b4.z, v3 = acc.w + b4.w;
    if (prelu) {
        float a = prelu_a[0];
        v0 = v0 >= 0.f ? v0 : a * v0;
        v1 = v1 >= 0.f ? v1 : a * v1;
        v2 = v2 >= 0.f ? v2 : a * v2;
        v3 = v3 >= 0.f ? v3 : a * v3;
    }
    size_t idx = (size_t)n * HC + t4;
    if (out) {
        *(float4*)(out + idx) = make_float4(v0, v1, v2, v3);
    }
    if (ohi) {
        __nv_bfloat16 h0 = __float2bfloat16(v0);
        __nv_bfloat16 h1 = __float2bfloat16(v1);
        __nv_bfloat16 h2 = __float2bfloat16(v2);
        __nv_bfloat16 h3 = __float2bfloat16(v3);
        __nv_bfloat162 hh01; hh01.x = h0; hh01.y = h1;
        __nv_bfloat162 hh23; hh23.x = h2; hh23.y = h3;
        *(__nv_bfloat162*)(ohi + idx)     = hh01;
        *(__nv_bfloat162*)(ohi + idx + 2) = hh23;
        __nv_bfloat162 ll01;
        ll01.x = __float2bfloat16(v0 - __bfloat162float(h0));
        ll01.y = __float2bfloat16(v1 - __bfloat162float(h1));
        __nv_bfloat162 ll23;
        ll23.x = __float2bfloat16(v2 - __bfloat162float(h2));
        ll23.y = __float2bfloat16(v3 - __bfloat162float(h3));
        *(__nv_bfloat162*)(olo + idx)     = ll01;
        *(__nv_bfloat162*)(olo + idx + 2) = ll23;
    }
}

// ---------------- host orchestration ----------------
static inline int ceil_div(int a, int b) { return (a + b - 1) / b; }

static void run_gemm(const __nv_bfloat16* Ahi, const __nv_bfloat16* Alo,
                     const __nv_bfloat16* Bhi, const __nv_bfloat16* Blo,
                     float* C, int M, int K, int N) {
    static int smem_set = 0;
    if (!smem_set) {
        cudaFuncSetAttribute(mma_gemm, cudaFuncAttributeMaxDynamicSharedMemorySize, G_SMEM);
        smem_set = 1;
    }
    dim3 grid(N / 128, ceil_div(M, 128));
    mma_gemm<<<grid, 256, G_SMEM>>>(Ahi, Alo, Bhi, Blo, C, M, K, N);
}

extern "C" void kernel_launch(void* const* d_in, const int* in_sizes, int n_in,
                              void* d_out, int out_size) {
    const float* x       = (const float*)d_in[0];
    const void*  eidx    = d_in[1];
    const float* W1      = (const float*)d_in[2];
    const float* a_src1  = (const float*)d_in[3];
    const float* a_dst1  = (const float*)d_in[4];
    const float* b1      = (const float*)d_in[5];
    const float* prelu_a = (const float*)d_in[6];
    const float* W2      = (const float*)d_in[7];
    const float* a_src2  = (const float*)d_in[8];
    const float* a_dst2  = (const float*)d_in[9];
    const float* b2      = (const float*)d_in[10];
    const float* Wd      = (const float*)d_in[11];
    const float* a_srcd  = (const float*)d_in[12];
    const float* a_dstd  = (const float*)d_in[13];
    const float* bd      = (const float*)d_in[14];

    const int HHc = in_sizes[3];          // 512
    const int H1  = 4;
    const int C1  = HHc / H1;             // 128
    const int M   = in_sizes[8];          // 256
    const int D   = in_sizes[12];         // 256
    const int N   = in_sizes[0] / D;      // 50000
    const int E   = in_sizes[1] / 2;      // 400000
    const int ET  = E + N;

    float* out   = (float*)d_out;
    float* z     = out;
    float* x_hat = out + (size_t)N * M;

    float *h1, *h2, *hd;
    float *as1, *ad1, *as2, *ad2, *asd, *add;
    __nv_bfloat16 *ahi, *alo, *wthi, *wtlo;
    int *cnt_p;
    cudaGetSymbolAddress((void**)&h1,  g_h1);
    cudaGetSymbolAddress((void**)&h2,  g_h2);
    cudaGetSymbolAddress((void**)&hd,  g_hd);
    cudaGetSymbolAddress((void**)&ahi, g_ahi);
    cudaGetSymbolAddress((void**)&alo, g_alo);
    cudaGetSymbolAddress((void**)&wthi, g_wthi);
    cudaGetSymbolAddress((void**)&wtlo, g_wtlo);
    cudaGetSymbolAddress((void**)&as1, g_as1);
    cudaGetSymbolAddress((void**)&ad1, g_ad1);
    cudaGetSymbolAddress((void**)&as2, g_as2);
    cudaGetSymbolAddress((void**)&ad2, g_ad2);
    cudaGetSymbolAddress((void**)&asd, g_asd);
    cudaGetSymbolAddress((void**)&add, g_add);
    cudaGetSymbolAddress((void**)&cnt_p, g_cnt);

    // ---- launches ordered so layer-1 mma_gemm lands in ncu's profiled slot ----
    split_kernel<<<ceil_div(N * D, 256), 256>>>(x, ahi, alo, N * D);
    wtsplit_kernel<<<ceil_div(D * HHc, 256), 256>>>(W1, wthi, wtlo, D, HHc);
    detect_kernel<<<1, 32>>>((const int*)eidx, E);
    run_gemm(ahi, alo, wthi, wtlo, h1, N, D, HHc);

    // ---- CSR build ----
    build_edges<<<ceil_div(ET, 256), 256>>>(eidx, E, N);
    zero_int<<<ceil_div(N, 256), 256>>>(cnt_p, N);
    hist_kernel<<<ceil_div(ET, 256), 256>>>(ET);
    scan_kernel<<<1, 1024>>>(N);
    copy_cursor<<<ceil_div(N, 256), 256>>>(N);
    scatter_kernel<<<ceil_div(ET, 256), 256>>>(ET);

    // ---- layer 1 rest ----
    alpha_kernel<<<ceil_div(N * H1 * 32, 256), 256>>>(h1, a_src1, a_dst1, as1, ad1, N, H1, C1);
    gat_aggregate<<<N, HHc / 4>>>(h1, as1, ad1, b1, nullptr, ahi, alo, H1, C1, 1, prelu_a);

    // ---- layer 2 ----
    wtsplit_kernel<<<ceil_div(HHc * M, 256), 256>>>(W2, wthi, wtlo, HHc, M);
    run_gemm(ahi, alo, wthi, wtlo, h2, N, HHc, M);
    alpha_kernel<<<ceil_div(N * 32, 256), 256>>>(h2, a_src2, a_dst2, as2, ad2, N, 1, M);
    gat_aggregate<<<N, M / 4>>>(h2, as2, ad2, b2, z, ahi, alo, 1, M, 0, prelu_a);

    // ---- decoder ----
    wtsplit_kernel<<<ceil_div(M * D, 256), 256>>>(Wd, wthi, wtlo, M, D);
    run_gemm(ahi, alo, wthi, wtlo, hd, N, M, D);
    alpha_kernel<<<ceil_div(N * 32, 256), 256>>>(hd, a_srcd, a_dstd, asd, add, N, 1, D);
    gat_aggregate<<<N, D / 4>>>(hd, asd, add, bd, x_hat, nullptr, nullptr, 1, D, 0, prelu_a);
}

// round 13
// speedup vs baseline: 1.4775x; 1.4775x over previous
#include <cuda_runtime.h>
#include <cuda_bf16.h>
#include <math.h>
#include <stdint.h>

// ---------------- problem-size maxima ----------------
#define MAXN   50000
#define MAXE   400000
#define MAXET  (MAXE + MAXN)
#define MAXHC  512
#define MAXM   256

// ---------------- device scratch ----------------
__device__ int   g_src [MAXET];
__device__ int   g_dst [MAXET];
__device__ int   g_srcs[MAXET];
__device__ int   g_cnt [MAXN];
__device__ int   g_rp  [MAXN + 1];
__device__ int   g_cur [MAXN];
__device__ int   g_is64;

__device__ float g_h1 [(size_t)MAXN * MAXHC];
__device__ float g_h2 [(size_t)MAXN * MAXM];
__device__ float g_hd [(size_t)MAXN * MAXM];
__device__ __nv_bfloat16 g_ahi[(size_t)MAXN * MAXHC];
__device__ __nv_bfloat16 g_alo[(size_t)MAXN * MAXHC];
__device__ __nv_bfloat16 g_wthi[512 * 512];
__device__ __nv_bfloat16 g_wtlo[512 * 512];
__device__ float g_as1[(size_t)MAXN * 4], g_ad1[(size_t)MAXN * 4];
__device__ float g_as2[MAXN], g_ad2[MAXN];
__device__ float g_asd[MAXN], g_add[MAXN];

// ---------------- PTX helpers ----------------
__device__ __forceinline__ uint32_t smem_u32(const void* p) {
    uint32_t a;
    asm("{ .reg .u64 t; cvta.to.shared.u64 t, %1; cvt.u32.u64 %0, t; }" : "=r"(a) : "l"(p));
    return a;
}
__device__ __forceinline__ void ldmx4(uint32_t* r, uint32_t addr) {
    asm volatile("ldmatrix.sync.aligned.m8n8.x4.shared.b16 {%0,%1,%2,%3}, [%4];"
        : "=r"(r[0]), "=r"(r[1]), "=r"(r[2]), "=r"(r[3]) : "r"(addr));
}
__device__ __forceinline__ void mma16816(float* c, const uint32_t* a,
                                         uint32_t b0, uint32_t b1) {
    asm volatile(
        "mma.sync.aligned.m16n8k16.row.col.f32.bf16.bf16.f32 "
        "{%0,%1,%2,%3}, {%4,%5,%6,%7}, {%8,%9}, {%0,%1,%2,%3};"
        : "+f"(c[0]), "+f"(c[1]), "+f"(c[2]), "+f"(c[3])
        : "r"(a[0]), "r"(a[1]), "r"(a[2]), "r"(a[3]), "r"(b0), "r"(b1));
}

// ---------------- graph-building kernels ----------------
__global__ void detect_kernel(const int* __restrict__ ei32, int E) {
    if (threadIdx.x == 0 && blockIdx.x == 0) {
        int nz = 0;
        int cnt = E < 64 ? E : 64;
        for (int i = 0; i < cnt; i++) nz |= ei32[2 * i + 1];
        g_is64 = (nz == 0) ? 1 : 0;
    }
}
__global__ void build_edges(const void* __restrict__ ei, int E, int Nn) {
    int i = blockIdx.x * blockDim.x + threadIdx.x;
    int tot = E + Nn;
    if (i >= tot) return;
    int s, d;
    if (i < E) {
        if (g_is64) {
            const long long* p = (const long long*)ei;
            s = (int)p[i]; d = (int)p[E + i];
        } else {
            const int* p = (const int*)ei;
            s = p[i]; d = p[E + i];
        }
    } else { s = d = i - E; }
    g_src[i] = s; g_dst[i] = d;
}
__global__ void zero_int(int* p, int n) {
    int i = blockIdx.x * blockDim.x + threadIdx.x;
    if (i < n) p[i] = 0;
}
__global__ void zero_f2(float* a, float* b, int n) {
    int i = blockIdx.x * blockDim.x + threadIdx.x;
    if (i < n) { a[i] = 0.f; b[i] = 0.f; }
}
__global__ void hist_kernel(int tot) {
    int i = blockIdx.x * blockDim.x + threadIdx.x;
    if (i < tot) atomicAdd(&g_cnt[g_dst[i]], 1);
}
__global__ void scan_kernel(int n) {
    __shared__ int sh[1024];
    __shared__ int carry;
    if (threadIdx.x == 0) carry = 0;
    __syncthreads();
    for (int base = 0; base < n; base += 1024) {
        int i = base + threadIdx.x;
        int v = (i < n) ? g_cnt[i] : 0;
        sh[threadIdx.x] = v;
        __syncthreads();
        for (int off = 1; off < 1024; off <<= 1) {
            int t = (threadIdx.x >= off) ? sh[threadIdx.x - off] : 0;
            __syncthreads();
            sh[threadIdx.x] += t;
            __syncthreads();
        }
        if (i < n) g_rp[i + 1] = sh[threadIdx.x] + carry;
        __syncthreads();
        if (threadIdx.x == 0) carry += sh[1023];
        __syncthreads();
    }
    if (threadIdx.x == 0) g_rp[0] = 0;
}
__global__ void copy_cursor(int n) {
    int i = blockIdx.x * blockDim.x + threadIdx.x;
    if (i < n) g_cur[i] = g_rp[i];
}
__global__ void scatter_kernel(int tot) {
    int i = blockIdx.x * blockDim.x + threadIdx.x;
    if (i >= tot) return;
    int d = g_dst[i];
    int pos = atomicAdd(&g_cur[d], 1);
    g_srcs[pos] = g_src[i];
}

// ---------------- bf16 split conversions ----------------
__global__ void split_kernel(const float* __restrict__ src,
                             __nv_bfloat16* __restrict__ hi,
                             __nv_bfloat16* __restrict__ lo, int total) {
    int i = blockIdx.x * blockDim.x + threadIdx.x;
    if (i >= total) return;
    float v = src[i];
    __nv_bfloat16 h = __float2bfloat16(v);
    hi[i] = h;
    lo[i] = __float2bfloat16(v - __bfloat162float(h));
}
__global__ void wtsplit_kernel(const float* __restrict__ W,
                               __nv_bfloat16* __restrict__ hi,
                               __nv_bfloat16* __restrict__ lo, int K, int N) {
    int idx = blockIdx.x * blockDim.x + threadIdx.x;
    if (idx >= K * N) return;
    int k = idx / N, n = idx - k * N;
    float v = W[idx];
    __nv_bfloat16 h = __float2bfloat16(v);
    hi[(size_t)n * K + k] = h;
    lo[(size_t)n * K + k] = __float2bfloat16(v - __bfloat162float(h));
}

// ---------------- split-bf16 tensor-core GEMM + fused alpha epilogue ---------
// C[M,N] = Ahi/lo[M,K] @ (Bt hi/lo[N,K])^T, fp32 accumulate.
// CTA tile 128x64, BK=32, 8 warps (4M x 2N), warp tile 32x32 (R9-proven form).
// Epilogue also accumulates alpha_s/alpha_d = C_row . a_src/a_dst per head
// via quad-reduce + atomicAdd (as_/ad_ must be zeroed before launch).
// Each 64-wide n-tile lies entirely within one head (head width C >= 128).
__global__ void __launch_bounds__(256, 2)
mma_gemm(const __nv_bfloat16* __restrict__ Ahi, const __nv_bfloat16* __restrict__ Alo,
         const __nv_bfloat16* __restrict__ Bhi, const __nv_bfloat16* __restrict__ Blo,
         float* __restrict__ C, int M, int K, int N,
         const float* __restrict__ asrc, const float* __restrict__ adst,
         float* __restrict__ as_, float* __restrict__ ad_, int H, int Ch) {
    __shared__ __align__(16) uint8_t sAh[128 * 80], sAl[128 * 80];
    __shared__ __align__(16) uint8_t sBh[64 * 80],  sBl[64 * 80];
    int tid = threadIdx.x, lane = tid & 31, wid = tid >> 5;
    int wm = wid & 3, wn = wid >> 2;
    int m0 = blockIdx.y * 128, n0 = blockIdx.x * 64;

    int lr = tid >> 2, lc = tid & 3;
    int gm0 = m0 + lr, gm1 = m0 + lr + 64;
    const size_t a0off = (size_t)gm0 * K + lc * 8;
    const size_t a1off = (size_t)gm1 * K + lc * 8;
    const size_t bOff  = (size_t)(n0 + lr) * K + lc * 8;
    uint32_t stA0 = (uint32_t)(lr * 80 + lc * 16);
    uint32_t stA1 = (uint32_t)((lr + 64) * 80 + lc * 16);

    uint32_t sAhB = smem_u32(sAh), sAlB = smem_u32(sAl);
    uint32_t sBhB = smem_u32(sBh), sBlB = smem_u32(sBl);

    uint32_t aoffs[2], boffs[2];
#pragma unroll
    for (int mt = 0; mt < 2; mt++)
        aoffs[mt] = (uint32_t)((wm * 32 + mt * 16 + (lane & 15)) * 80 + (lane >> 4) * 16);
#pragma unroll
    for (int p = 0; p < 2; p++)
        boffs[p] = (uint32_t)((wn * 32 + p * 16 + ((lane >> 3) & 1) * 8 + (lane & 7)) * 80
                              + (lane >> 4) * 16);

    float acc[2][4][4];
#pragma unroll
    for (int i = 0; i < 2; i++)
#pragma unroll
        for (int j = 0; j < 4; j++)
#pragma unroll
            for (int q = 0; q < 4; q++) acc[i][j][q] = 0.f;

    const uint4 z4 = make_uint4(0, 0, 0, 0);
    uint4 pa0h, pa1h, pa0l, pa1l, pbh, pbl;
    pa0h = (gm0 < M) ? *(const uint4*)(Ahi + a0off) : z4;
    pa1h = (gm1 < M) ? *(const uint4*)(Ahi + a1off) : z4;
    pa0l = (gm0 < M) ? *(const uint4*)(Alo + a0off) : z4;
    pa1l = (gm1 < M) ? *(const uint4*)(Alo + a1off) : z4;
    pbh  = *(const uint4*)(Bhi + bOff);
    pbl  = *(const uint4*)(Blo + bOff);

    int nch = K >> 5;
    for (int ch = 0; ch < nch; ch++) {
        *(uint4*)(sAh + stA0) = pa0h;
        *(uint4*)(sAh + stA1) = pa1h;
        *(uint4*)(sAl + stA0) = pa0l;
        *(uint4*)(sAl + stA1) = pa1l;
        *(uint4*)(sBh + stA0) = pbh;
        *(uint4*)(sBl + stA0) = pbl;
        __syncthreads();

        if (ch + 1 < nch) {
            int k8 = (ch + 1) * 32;
            pa0h = (gm0 < M) ? *(const uint4*)(Ahi + a0off + k8) : z4;
            pa1h = (gm1 < M) ? *(const uint4*)(Ahi + a1off + k8) : z4;
            pa0l = (gm0 < M) ? *(const uint4*)(Alo + a0off + k8) : z4;
            pa1l = (gm1 < M) ? *(const uint4*)(Alo + a1off + k8) : z4;
            pbh  = *(const uint4*)(Bhi + bOff + k8);
            pbl  = *(const uint4*)(Blo + bOff + k8);
        }

#pragma unroll
        for (int ks = 0; ks < 2; ks++) {
            uint32_t AH[2][4], AL[2][4], BH[2][4], BL[2][4];
            ldmx4(AH[0], sAhB + aoffs[0] + ks * 32);
            ldmx4(AH[1], sAhB + aoffs[1] + ks * 32);
            ldmx4(AL[0], sAlB + aoffs[0] + ks * 32);
            ldmx4(AL[1], sAlB + aoffs[1] + ks * 32);
            ldmx4(BH[0], sBhB + boffs[0] + ks * 32);
            ldmx4(BH[1], sBhB + boffs[1] + ks * 32);
            ldmx4(BL[0], sBlB + boffs[0] + ks * 32);
            ldmx4(BL[1], sBlB + boffs[1] + ks * 32);
#pragma unroll
            for (int mt = 0; mt < 2; mt++) {
#pragma unroll
                for (int p = 0; p < 2; p++) {
                    mma16816(acc[mt][p * 2 + 0], AH[mt], BH[p][0], BH[p][2]);
                    mma16816(acc[mt][p * 2 + 1], AH[mt], BH[p][1], BH[p][3]);
                    mma16816(acc[mt][p * 2 + 0], AH[mt], BL[p][0], BL[p][2]);
                    mma16816(acc[mt][p * 2 + 1], AH[mt], BL[p][1], BL[p][3]);
                    mma16816(acc[mt][p * 2 + 0], AL[mt], BH[p][0], BH[p][2]);
                    mma16816(acc[mt][p * 2 + 1], AL[mt], BH[p][1], BH[p][3]);
                }
            }
        }
        __syncthreads();
    }

    // ---- epilogue: store C + fused alpha partials ----
    int hh = n0 / Ch;   // head index of this CTA's column range
#pragma unroll
    for (int mt = 0; mt < 2; mt++) {
        int gr0 = m0 + wm * 32 + mt * 16 + (lane >> 2);
        int gr1 = gr0 + 8;
        float ps0 = 0.f, pd0 = 0.f, ps1 = 0.f, pd1 = 0.f;
#pragma unroll
        for (int nt = 0; nt < 4; nt++) {
            int gc = n0 + wn * 32 + nt * 8 + (lane & 3) * 2;
            float a0 = asrc[gc], a1 = asrc[gc + 1];
            float d0 = adst[gc], d1 = adst[gc + 1];
            ps0 = fmaf(acc[mt][nt][0], a0, fmaf(acc[mt][nt][1], a1, ps0));
            pd0 = fmaf(acc[mt][nt][0], d0, fmaf(acc[mt][nt][1], d1, pd0));
            ps1 = fmaf(acc[mt][nt][2], a0, fmaf(acc[mt][nt][3], a1, ps1));
            pd1 = fmaf(acc[mt][nt][2], d0, fmaf(acc[mt][nt][3], d1, pd1));
            if (gr0 < M)
                *(float2*)(C + (size_t)gr0 * N + gc) = make_float2(acc[mt][nt][0], acc[mt][nt][1]);
            if (gr1 < M)
                *(float2*)(C + (size_t)gr1 * N + gc) = make_float2(acc[mt][nt][2], acc[mt][nt][3]);
        }
        // reduce across the 4 lanes of each quad (they share gr0/gr1)
#pragma unroll
        for (int o = 1; o <= 2; o <<= 1) {
            ps0 += __shfl_xor_sync(0xffffffffu, ps0, o);
            pd0 += __shfl_xor_sync(0xffffffffu, pd0, o);
            ps1 += __shfl_xor_sync(0xffffffffu, ps1, o);
            pd1 += __shfl_xor_sync(0xffffffffu, pd1, o);
        }
        if ((lane & 3) == 0) {
            if (gr0 < M) {
                atomicAdd(&as_[(size_t)gr0 * H + hh], ps0);
                atomicAdd(&ad_[(size_t)gr0 * H + hh], pd0);
            }
            if (gr1 < M) {
                atomicAdd(&as_[(size_t)gr1 * H + hh], ps1);
                atomicAdd(&ad_[(size_t)gr1 * H + hh], pd1);
            }
        }
    }
}

// ---------------- GAT segment-softmax + aggregate (float4 channels) ----------
// blockDim = H*C/4; each thread owns 4 consecutive channels.
#define CHUNK 64
__global__ void gat_aggregate(const float* __restrict__ feat,
                              const float* __restrict__ as_,
                              const float* __restrict__ ad_,
                              const float* __restrict__ bias,
                              float* __restrict__ out,            // nullable
                              __nv_bfloat16* __restrict__ ohi,    // nullable
                              __nv_bfloat16* __restrict__ olo,
                              int H, int C, int prelu,
                              const float* __restrict__ prelu_a) {
    int n = blockIdx.x;
    int t = threadIdx.x;
    int HC = H * C;
    int t4 = t * 4;
    int h = t4 / C;
    __shared__ float sw[4 * CHUNK];
    __shared__ int   ssrc[CHUNK];
    int s0 = g_rp[n], s1 = g_rp[n + 1];
    int warp = t >> 5, lane = t & 31;

    // phase 1: softmax stats in head-warp registers
    float m = 0.f, rdn = 0.f, ad = 0.f;
    if (warp < H) {
        ad = ad_[(size_t)n * H + warp];
        m = -INFINITY;
        for (int k = s0 + lane; k < s1; k += 32) {
            float e = as_[(size_t)g_srcs[k] * H + warp] + ad;
            e = e > 0.f ? e : 0.2f * e;
            m = fmaxf(m, e);
        }
#pragma unroll
        for (int o = 16; o; o >>= 1) m = fmaxf(m, __shfl_xor_sync(0xffffffffu, m, o));
        float ds = 0.f;
        for (int k = s0 + lane; k < s1; k += 32) {
            float e = as_[(size_t)g_srcs[k] * H + warp] + ad;
            e = e > 0.f ? e : 0.2f * e;
            ds += __expf(e - m);
        }
#pragma unroll
        for (int o = 16; o; o >>= 1) ds += __shfl_xor_sync(0xffffffffu, ds, o);
        rdn = 1.f / (ds + 1e-16f);
    }

    // phase 2: chunked weights + float4 gather/accumulate
    float4 acc = make_float4(0.f, 0.f, 0.f, 0.f);
    for (int base = s0; base < s1; base += CHUNK) {
        int count = min(CHUNK, s1 - base);
        __syncthreads();
        if (warp < H) {
            for (int j = lane; j < count; j += 32) {
                int s = g_srcs[base + j];
                if (warp == 0) ssrc[j] = s;
                float e = as_[(size_t)s * H + warp] + ad;
                e = e > 0.f ? e : 0.2f * e;
                sw[warp * CHUNK + j] = __expf(e - m) * rdn;
            }
        }
        __syncthreads();
        const float* swh = sw + h * CHUNK;
        for (int j = 0; j < count; j++) {
            float4 f = *(const float4*)(feat + (size_t)ssrc[j] * HC + t4);
            float w = swh[j];
            acc.x = fmaf(f.x, w, acc.x);
            acc.y = fmaf(f.y, w, acc.y);
            acc.z = fmaf(f.z, w, acc.z);
            acc.w = fmaf(f.w, w, acc.w);
        }
    }

    float4 b4 = *(const float4*)(bias + t4);
    float v0 = acc.x + b4.x, v1 = acc.y + b4.y, v2 = acc.z + b4.z, v3 = acc.w + b4.w;
    if (prelu) {
        float a = prelu_a[0];
        v0 = v0 >= 0.f ? v0 : a * v0;
        v1 = v1 >= 0.f ? v1 : a * v1;
        v2 = v2 >= 0.f ? v2 : a * v2;
        v3 = v3 >= 0.f ? v3 : a * v3;
    }
    size_t idx = (size_t)n * HC + t4;
    if (out) {
        *(float4*)(out + idx) = make_float4(v0, v1, v2, v3);
    }
    if (ohi) {
        __nv_bfloat16 h0 = __float2bfloat16(v0);
        __nv_bfloat16 h1 = __float2bfloat16(v1);
        __nv_bfloat16 h2 = __float2bfloat16(v2);
        __nv_bfloat16 h3 = __float2bfloat16(v3);
        __nv_bfloat162 hh01; hh01.x = h0; hh01.y = h1;
        __nv_bfloat162 hh23; hh23.x = h2; hh23.y = h3;
        *(__nv_bfloat162*)(ohi + idx)     = hh01;
        *(__nv_bfloat162*)(ohi + idx + 2) = hh23;
        __nv_bfloat162 ll01;
        ll01.x = __float2bfloat16(v0 - __bfloat162float(h0));
        ll01.y = __float2bfloat16(v1 - __bfloat162float(h1));
        __nv_bfloat162 ll23;
        ll23.x = __float2bfloat16(v2 - __bfloat162float(h2));
        ll23.y = __float2bfloat16(v3 - __bfloat162float(h3));
        *(__nv_bfloat162*)(olo + idx)     = ll01;
        *(__nv_bfloat162*)(olo + idx + 2) = ll23;
    }
}

// ---------------- host orchestration ----------------
static inline int ceil_div(int a, int b) { return (a + b - 1) / b; }

static void run_gemm(const __nv_bfloat16* Ahi, const __nv_bfloat16* Alo,
                     const __nv_bfloat16* Bhi, const __nv_bfloat16* Blo,
                     float* C, int M, int K, int N,
                     const float* asrc, const float* adst,
                     float* as_, float* ad_, int H, int Ch) {
    dim3 grid(N / 64, ceil_div(M, 128));
    mma_gemm<<<grid, 256>>>(Ahi, Alo, Bhi, Blo, C, M, K, N,
                            asrc, adst, as_, ad_, H, Ch);
}

extern "C" void kernel_launch(void* const* d_in, const int* in_sizes, int n_in,
                              void* d_out, int out_size) {
    const float* x       = (const float*)d_in[0];
    const void*  eidx    = d_in[1];
    const float* W1      = (const float*)d_in[2];
    const float* a_src1  = (const float*)d_in[3];
    const float* a_dst1  = (const float*)d_in[4];
    const float* b1      = (const float*)d_in[5];
    const float* prelu_a = (const float*)d_in[6];
    const float* W2      = (const float*)d_in[7];
    const float* a_src2  = (const float*)d_in[8];
    const float* a_dst2  = (const float*)d_in[9];
    const float* b2      = (const float*)d_in[10];
    const float* Wd      = (const float*)d_in[11];
    const float* a_srcd  = (const float*)d_in[12];
    const float* a_dstd  = (const float*)d_in[13];
    const float* bd      = (const float*)d_in[14];

    const int HHc = in_sizes[3];          // 512
    const int H1  = 4;
    const int C1  = HHc / H1;             // 128
    const int M   = in_sizes[8];          // 256
    const int D   = in_sizes[12];         // 256
    const int N   = in_sizes[0] / D;      // 50000
    const int E   = in_sizes[1] / 2;      // 400000
    const int ET  = E + N;

    float* out   = (float*)d_out;
    float* z     = out;
    float* x_hat = out + (size_t)N * M;

    float *h1, *h2, *hd;
    float *as1, *ad1, *as2, *ad2, *asd, *add;
    __nv_bfloat16 *ahi, *alo, *wthi, *wtlo;
    int *cnt_p;
    cudaGetSymbolAddress((void**)&h1,  g_h1);
    cudaGetSymbolAddress((void**)&h2,  g_h2);
    cudaGetSymbolAddress((void**)&hd,  g_hd);
    cudaGetSymbolAddress((void**)&ahi, g_ahi);
    cudaGetSymbolAddress((void**)&alo, g_alo);
    cudaGetSymbolAddress((void**)&wthi, g_wthi);
    cudaGetSymbolAddress((void**)&wtlo, g_wtlo);
    cudaGetSymbolAddress((void**)&as1, g_as1);
    cudaGetSymbolAddress((void**)&ad1, g_ad1);
    cudaGetSymbolAddress((void**)&as2, g_as2);
    cudaGetSymbolAddress((void**)&ad2, g_ad2);
    cudaGetSymbolAddress((void**)&asd, g_asd);
    cudaGetSymbolAddress((void**)&add, g_add);
    cudaGetSymbolAddress((void**)&cnt_p, g_cnt);

    // ---- launches ordered so layer-1 mma_gemm stays in ncu's profiled slot ----
    split_kernel<<<ceil_div(N * D, 256), 256>>>(x, ahi, alo, N * D);
    wtsplit_kernel<<<ceil_div(D * HHc, 256), 256>>>(W1, wthi, wtlo, D, HHc);
    zero_f2<<<ceil_div(N * H1, 256), 256>>>(as1, ad1, N * H1);
    run_gemm(ahi, alo, wthi, wtlo, h1, N, D, HHc, a_src1, a_dst1, as1, ad1, H1, C1);

    // ---- CSR build ----
    detect_kernel<<<1, 32>>>((const int*)eidx, E);
    build_edges<<<ceil_div(ET, 256), 256>>>(eidx, E, N);
    zero_int<<<ceil_div(N, 256), 256>>>(cnt_p, N);
    hist_kernel<<<ceil_div(ET, 256), 256>>>(ET);
    scan_kernel<<<1, 1024>>>(N);
    copy_cursor<<<ceil_div(N, 256), 256>>>(N);
    scatter_kernel<<<ceil_div(ET, 256), 256>>>(ET);

    // ---- layer 1 aggregate (+PReLU, emits split bf16 for next GEMM) ----
    gat_aggregate<<<N, HHc / 4>>>(h1, as1, ad1, b1, nullptr, ahi, alo, H1, C1, 1, prelu_a);

    // ---- layer 2 ----
    wtsplit_kernel<<<ceil_div(HHc * M, 256), 256>>>(W2, wthi, wtlo, HHc, M);
    zero_f2<<<ceil_div(N, 256), 256>>>(as2, ad2, N);
    run_gemm(ahi, alo, wthi, wtlo, h2, N, HHc, M, a_src2, a_dst2, as2, ad2, 1, M);
    gat_aggregate<<<N, M / 4>>>(h2, as2, ad2, b2, z, ahi, alo, 1, M, 0, prelu_a);

    // ---- decoder ----
    wtsplit_kernel<<<ceil_div(M * D, 256), 256>>>(Wd, wthi, wtlo, M, D);
    zero_f2<<<ceil_div(N, 256), 256>>>(asd, add, N);
    run_gemm(ahi, alo, wthi, wtlo, hd, N, M, D, a_srcd, a_dstd, asd, add, 1, D);
    gat_aggregate<<<N, D / 4>>>(hd, asd, add, bd, x_hat, nullptr, nullptr, 1, D, 0, prelu_a);
}

// round 14
// speedup vs baseline: 1.6786x; 1.1361x over previous
#include <cuda_runtime.h>
#include <cuda_bf16.h>
#include <math.h>
#include <stdint.h>

// ---------------- problem-size maxima ----------------
#define MAXN   50000
#define MAXE   400000
#define MAXET  (MAXE + MAXN)
#define MAXHC  512
#define MAXM   256

// ---------------- device scratch ----------------
__device__ int   g_src [MAXET];
__device__ int   g_dst [MAXET];
__device__ int   g_srcs[MAXET];
__device__ int   g_cnt [MAXN];
__device__ int   g_rp  [MAXN + 1];
__device__ int   g_cur [MAXN];
__device__ int   g_bsum[64];

__device__ float g_h1 [(size_t)MAXN * MAXHC];
__device__ float g_h2 [(size_t)MAXN * MAXM];
__device__ float g_hd [(size_t)MAXN * MAXM];
__device__ __nv_bfloat16 g_ahi[(size_t)MAXN * MAXHC];
__device__ __nv_bfloat16 g_alo[(size_t)MAXN * MAXHC];
__device__ __nv_bfloat16 g_wthi[512 * 512];
__device__ __nv_bfloat16 g_wtlo[512 * 512];
__device__ float g_as1[(size_t)MAXN * 4], g_ad1[(size_t)MAXN * 4];
__device__ float g_as2[MAXN], g_ad2[MAXN];
__device__ float g_asd[MAXN], g_add[MAXN];

// ---------------- PTX helpers ----------------
__device__ __forceinline__ uint32_t smem_u32(const void* p) {
    uint32_t a;
    asm("{ .reg .u64 t; cvta.to.shared.u64 t, %1; cvt.u32.u64 %0, t; }" : "=r"(a) : "l"(p));
    return a;
}
__device__ __forceinline__ void ldmx4(uint32_t* r, uint32_t addr) {
    asm volatile("ldmatrix.sync.aligned.m8n8.x4.shared.b16 {%0,%1,%2,%3}, [%4];"
        : "=r"(r[0]), "=r"(r[1]), "=r"(r[2]), "=r"(r[3]) : "r"(addr));
}
__device__ __forceinline__ void mma16816(float* c, const uint32_t* a,
                                         uint32_t b0, uint32_t b1) {
    asm volatile(
        "mma.sync.aligned.m16n8k16.row.col.f32.bf16.bf16.f32 "
        "{%0,%1,%2,%3}, {%4,%5,%6,%7}, {%8,%9}, {%0,%1,%2,%3};"
        : "+f"(c[0]), "+f"(c[1]), "+f"(c[2]), "+f"(c[3])
        : "r"(a[0]), "r"(a[1]), "r"(a[2]), "r"(a[3]), "r"(b0), "r"(b1));
}
// 8 fp32 (in two uint4) -> hi/lo bf16 split packed as two uint4 (8 bf16 each)
__device__ __forceinline__ void cvt8(uint4 r0, uint4 r1, uint4& h, uint4& l) {
    float v[8];
    *(uint4*)&v[0] = r0; *(uint4*)&v[4] = r1;
    __nv_bfloat162 hh[4], ll[4];
#pragma unroll
    for (int i = 0; i < 4; i++) {
        __nv_bfloat16 a = __float2bfloat16(v[2 * i]);
        __nv_bfloat16 b = __float2bfloat16(v[2 * i + 1]);
        hh[i].x = a; hh[i].y = b;
        ll[i].x = __float2bfloat16(v[2 * i]     - __bfloat162float(a));
        ll[i].y = __float2bfloat16(v[2 * i + 1] - __bfloat162float(b));
    }
    h = *(uint4*)hh; l = *(uint4*)ll;
}

// ---------------- graph-building kernels ----------------
__global__ void build_edges(const void* __restrict__ ei, int E, int Nn) {
    __shared__ int s_is64;
    if (threadIdx.x == 0) {
        const int* p = (const int*)ei;
        int nz = 0;
        int cnt = E < 64 ? E : 64;
        for (int i = 0; i < cnt; i++) nz |= p[2 * i + 1];
        s_is64 = (nz == 0) ? 1 : 0;
    }
    __syncthreads();
    int i = blockIdx.x * blockDim.x + threadIdx.x;
    int tot = E + Nn;
    if (i >= tot) return;
    int s, d;
    if (i < E) {
        if (s_is64) {
            const long long* p = (const long long*)ei;
            s = (int)p[i]; d = (int)p[E + i];
        } else {
            const int* p = (const int*)ei;
            s = p[i]; d = p[E + i];
        }
    } else { s = d = i - E; }
    g_src[i] = s; g_dst[i] = d;
}
__global__ void zero_int(int* p, int n) {
    int i = blockIdx.x * blockDim.x + threadIdx.x;
    if (i < n) p[i] = 0;
}
__global__ void zero_f2(float* a, float* b, int n) {
    int i = blockIdx.x * blockDim.x + threadIdx.x;
    if (i < n) { a[i] = 0.f; b[i] = 0.f; }
}
__global__ void hist_kernel(int tot) {
    int i = blockIdx.x * blockDim.x + threadIdx.x;
    if (i < tot) atomicAdd(&g_cnt[g_dst[i]], 1);
}
// two-level scan: per-block inclusive scans + block sums
__global__ void scan1_kernel(int n) {
    __shared__ int sh[1024];
    int tx = threadIdx.x;
    int i = blockIdx.x * 1024 + tx;
    int v = (i < n) ? g_cnt[i] : 0;
    sh[tx] = v;
    __syncthreads();
    for (int off = 1; off < 1024; off <<= 1) {
        int t = (tx >= off) ? sh[tx - off] : 0;
        __syncthreads();
        sh[tx] += t;
        __syncthreads();
    }
    if (i < n) g_rp[i + 1] = sh[tx];
    if (tx == 1023) g_bsum[blockIdx.x] = sh[1023];
}
__global__ void scan2_kernel(int nb) {   // 1 block, 64 threads
    __shared__ int sh[64];
    int tx = threadIdx.x;
    int v = (tx < nb) ? g_bsum[tx] : 0;
    sh[tx] = v;
    __syncthreads();
    for (int off = 1; off < 64; off <<= 1) {
        int t = (tx >= off) ? sh[tx - off] : 0;
        __syncthreads();
        sh[tx] += t;
        __syncthreads();
    }
    if (tx < nb) g_bsum[tx] = sh[tx];   // inclusive block sums
}
__global__ void scan3_kernel(int n) {
    int i = blockIdx.x * blockDim.x + threadIdx.x;
    if (i == 0) g_rp[0] = 0;
    if (i < n) {
        int b = i >> 10;
        if (b > 0) g_rp[i + 1] += g_bsum[b - 1];
    }
}
__global__ void copy_cursor(int n) {
    int i = blockIdx.x * blockDim.x + threadIdx.x;
    if (i < n) g_cur[i] = g_rp[i];
}
__global__ void scatter_kernel(int tot) {
    int i = blockIdx.x * blockDim.x + threadIdx.x;
    if (i >= tot) return;
    int d = g_dst[i];
    int pos = atomicAdd(&g_cur[d], 1);
    g_srcs[pos] = g_src[i];
}

// ---------------- bf16 split of W^T ----------------
__global__ void wtsplit_kernel(const float* __restrict__ W,
                               __nv_bfloat16* __restrict__ hi,
                               __nv_bfloat16* __restrict__ lo, int K, int N) {
    int idx = blockIdx.x * blockDim.x + threadIdx.x;
    if (idx >= K * N) return;
    int k = idx / N, n = idx - k * N;
    float v = W[idx];
    __nv_bfloat16 h = __float2bfloat16(v);
    hi[(size_t)n * K + k] = h;
    lo[(size_t)n * K + k] = __float2bfloat16(v - __bfloat162float(h));
}

// ---------------- split-bf16 tensor-core GEMM + fused alpha epilogue ---------
// C[M,N] = A[M,K] @ (Bt hi/lo[N,K])^T, fp32 accumulate.
// A is either presplit bf16 (Ahi/Alo) or raw fp32 (a_fp32=1, split in-kernel).
// CTA tile 128x64, BK=32, 8 warps (4M x 2N), warp tile 32x32.
// Epilogue accumulates alpha_s/alpha_d (as_/ad_ must be zeroed before launch).
__global__ void __launch_bounds__(256, 2)
mma_gemm(const __nv_bfloat16* __restrict__ Ahi, const __nv_bfloat16* __restrict__ Alo,
         const __nv_bfloat16* __restrict__ Bhi, const __nv_bfloat16* __restrict__ Blo,
         float* __restrict__ C, int M, int K, int N,
         const float* __restrict__ asrc, const float* __restrict__ adst,
         float* __restrict__ as_, float* __restrict__ ad_, int H, int Ch,
         int a_fp32) {
    __shared__ __align__(16) uint8_t sAh[128 * 80], sAl[128 * 80];
    __shared__ __align__(16) uint8_t sBh[64 * 80],  sBl[64 * 80];
    int tid = threadIdx.x, lane = tid & 31, wid = tid >> 5;
    int wm = wid & 3, wn = wid >> 2;
    int m0 = blockIdx.y * 128, n0 = blockIdx.x * 64;

    int lr = tid >> 2, lc = tid & 3;
    int gm0 = m0 + lr, gm1 = m0 + lr + 64;
    const size_t a0off = (size_t)gm0 * K + lc * 8;
    const size_t a1off = (size_t)gm1 * K + lc * 8;
    const size_t bOff  = (size_t)(n0 + lr) * K + lc * 8;
    uint32_t stA0 = (uint32_t)(lr * 80 + lc * 16);
    uint32_t stA1 = (uint32_t)((lr + 64) * 80 + lc * 16);
    const float* X = (const float*)Ahi;   // when a_fp32

    uint32_t sAhB = smem_u32(sAh), sAlB = smem_u32(sAl);
    uint32_t sBhB = smem_u32(sBh), sBlB = smem_u32(sBl);

    uint32_t aoffs[2], boffs[2];
#pragma unroll
    for (int mt = 0; mt < 2; mt++)
        aoffs[mt] = (uint32_t)((wm * 32 + mt * 16 + (lane & 15)) * 80 + (lane >> 4) * 16);
#pragma unroll
    for (int p = 0; p < 2; p++)
        boffs[p] = (uint32_t)((wn * 32 + p * 16 + ((lane >> 3) & 1) * 8 + (lane & 7)) * 80
                              + (lane >> 4) * 16);

    float acc[2][4][4];
#pragma unroll
    for (int i = 0; i < 2; i++)
#pragma unroll
        for (int j = 0; j < 4; j++)
#pragma unroll
            for (int q = 0; q < 4; q++) acc[i][j][q] = 0.f;

    const uint4 z4 = make_uint4(0, 0, 0, 0);
    uint4 pa0h, pa1h, pa0l, pa1l, pbh, pbl;
    if (a_fp32) {
        const uint4* p0 = (const uint4*)(X + a0off);
        const uint4* p1 = (const uint4*)(X + a1off);
        pa0h = (gm0 < M) ? p0[0] : z4;  pa0l = (gm0 < M) ? p0[1] : z4;
        pa1h = (gm1 < M) ? p1[0] : z4;  pa1l = (gm1 < M) ? p1[1] : z4;
    } else {
        pa0h = (gm0 < M) ? *(const uint4*)(Ahi + a0off) : z4;
        pa1h = (gm1 < M) ? *(const uint4*)(Ahi + a1off) : z4;
        pa0l = (gm0 < M) ? *(const uint4*)(Alo + a0off) : z4;
        pa1l = (gm1 < M) ? *(const uint4*)(Alo + a1off) : z4;
    }
    pbh = *(const uint4*)(Bhi + bOff);
    pbl = *(const uint4*)(Blo + bOff);

    int nch = K >> 5;
    for (int ch = 0; ch < nch; ch++) {
        if (a_fp32) {
            uint4 h0, l0, h1, l1;
            cvt8(pa0h, pa0l, h0, l0);
            cvt8(pa1h, pa1l, h1, l1);
            *(uint4*)(sAh + stA0) = h0;
            *(uint4*)(sAl + stA0) = l0;
            *(uint4*)(sAh + stA1) = h1;
            *(uint4*)(sAl + stA1) = l1;
        } else {
            *(uint4*)(sAh + stA0) = pa0h;
            *(uint4*)(sAh + stA1) = pa1h;
            *(uint4*)(sAl + stA0) = pa0l;
            *(uint4*)(sAl + stA1) = pa1l;
        }
        *(uint4*)(sBh + stA0) = pbh;
        *(uint4*)(sBl + stA0) = pbl;
        __syncthreads();

        if (ch + 1 < nch) {
            int k8 = (ch + 1) * 32;
            if (a_fp32) {
                const uint4* p0 = (const uint4*)(X + a0off + k8);
                const uint4* p1 = (const uint4*)(X + a1off + k8);
                pa0h = (gm0 < M) ? p0[0] : z4;  pa0l = (gm0 < M) ? p0[1] : z4;
                pa1h = (gm1 < M) ? p1[0] : z4;  pa1l = (gm1 < M) ? p1[1] : z4;
            } else {
                pa0h = (gm0 < M) ? *(const uint4*)(Ahi + a0off + k8) : z4;
                pa1h = (gm1 < M) ? *(const uint4*)(Ahi + a1off + k8) : z4;
                pa0l = (gm0 < M) ? *(const uint4*)(Alo + a0off + k8) : z4;
                pa1l = (gm1 < M) ? *(const uint4*)(Alo + a1off + k8) : z4;
            }
            pbh = *(const uint4*)(Bhi + bOff + k8);
            pbl = *(const uint4*)(Blo + bOff + k8);
        }

#pragma unroll
        for (int ks = 0; ks < 2; ks++) {
            uint32_t AH[2][4], AL[2][4], BH[2][4], BL[2][4];
            ldmx4(AH[0], sAhB + aoffs[0] + ks * 32);
            ldmx4(AH[1], sAhB + aoffs[1] + ks * 32);
            ldmx4(AL[0], sAlB + aoffs[0] + ks * 32);
            ldmx4(AL[1], sAlB + aoffs[1] + ks * 32);
            ldmx4(BH[0], sBhB + boffs[0] + ks * 32);
            ldmx4(BH[1], sBhB + boffs[1] + ks * 32);
            ldmx4(BL[0], sBlB + boffs[0] + ks * 32);
            ldmx4(BL[1], sBlB + boffs[1] + ks * 32);
#pragma unroll
            for (int mt = 0; mt < 2; mt++) {
#pragma unroll
                for (int p = 0; p < 2; p++) {
                    mma16816(acc[mt][p * 2 + 0], AH[mt], BH[p][0], BH[p][2]);
                    mma16816(acc[mt][p * 2 + 1], AH[mt], BH[p][1], BH[p][3]);
                    mma16816(acc[mt][p * 2 + 0], AH[mt], BL[p][0], BL[p][2]);
                    mma16816(acc[mt][p * 2 + 1], AH[mt], BL[p][1], BL[p][3]);
                    mma16816(acc[mt][p * 2 + 0], AL[mt], BH[p][0], BH[p][2]);
                    mma16816(acc[mt][p * 2 + 1], AL[mt], BH[p][1], BH[p][3]);
                }
            }
        }
        __syncthreads();
    }

    // ---- epilogue: store C + fused alpha partials ----
    int hh = n0 / Ch;
#pragma unroll
    for (int mt = 0; mt < 2; mt++) {
        int gr0 = m0 + wm * 32 + mt * 16 + (lane >> 2);
        int gr1 = gr0 + 8;
        float ps0 = 0.f, pd0 = 0.f, ps1 = 0.f, pd1 = 0.f;
#pragma unroll
        for (int nt = 0; nt < 4; nt++) {
            int gc = n0 + wn * 32 + nt * 8 + (lane & 3) * 2;
            float a0 = asrc[gc], a1 = asrc[gc + 1];
            float d0 = adst[gc], d1 = adst[gc + 1];
            ps0 = fmaf(acc[mt][nt][0], a0, fmaf(acc[mt][nt][1], a1, ps0));
            pd0 = fmaf(acc[mt][nt][0], d0, fmaf(acc[mt][nt][1], d1, pd0));
            ps1 = fmaf(acc[mt][nt][2], a0, fmaf(acc[mt][nt][3], a1, ps1));
            pd1 = fmaf(acc[mt][nt][2], d0, fmaf(acc[mt][nt][3], d1, pd1));
            if (gr0 < M)
                *(float2*)(C + (size_t)gr0 * N + gc) = make_float2(acc[mt][nt][0], acc[mt][nt][1]);
            if (gr1 < M)
                *(float2*)(C + (size_t)gr1 * N + gc) = make_float2(acc[mt][nt][2], acc[mt][nt][3]);
        }
#pragma unroll
        for (int o = 1; o <= 2; o <<= 1) {
            ps0 += __shfl_xor_sync(0xffffffffu, ps0, o);
            pd0 += __shfl_xor_sync(0xffffffffu, pd0, o);
            ps1 += __shfl_xor_sync(0xffffffffu, ps1, o);
            pd1 += __shfl_xor_sync(0xffffffffu, pd1, o);
        }
        if ((lane & 3) == 0) {
            if (gr0 < M) {
                atomicAdd(&as_[(size_t)gr0 * H + hh], ps0);
                atomicAdd(&ad_[(size_t)gr0 * H + hh], pd0);
            }
            if (gr1 < M) {
                atomicAdd(&as_[(size_t)gr1 * H + hh], ps1);
                atomicAdd(&ad_[(size_t)gr1 * H + hh], pd1);
            }
        }
    }
}

// ---------------- GAT segment-softmax + aggregate (float4 channels) ----------
#define CHUNK 64
__global__ void gat_aggregate(const float* __restrict__ feat,
                              const float* __restrict__ as_,
                              const float* __restrict__ ad_,
                              const float* __restrict__ bias,
                              float* __restrict__ out,            // nullable
                              __nv_bfloat16* __restrict__ ohi,    // nullable
                              __nv_bfloat16* __restrict__ olo,
                              int H, int C, int prelu,
                              const float* __restrict__ prelu_a) {
    int n = blockIdx.x;
    int t = threadIdx.x;
    int HC = H * C;
    int t4 = t * 4;
    int h = t4 / C;
    __shared__ float sw[4 * CHUNK];
    __shared__ int   ssrc[CHUNK];
    int s0 = g_rp[n], s1 = g_rp[n + 1];
    int warp = t >> 5, lane = t & 31;

    float m = 0.f, rdn = 0.f, ad = 0.f;
    if (warp < H) {
        ad = ad_[(size_t)n * H + warp];
        m = -INFINITY;
        for (int k = s0 + lane; k < s1; k += 32) {
            float e = as_[(size_t)g_srcs[k] * H + warp] + ad;
            e = e > 0.f ? e : 0.2f * e;
            m = fmaxf(m, e);
        }
#pragma unroll
        for (int o = 16; o; o >>= 1) m = fmaxf(m, __shfl_xor_sync(0xffffffffu, m, o));
        float ds = 0.f;
        for (int k = s0 + lane; k < s1; k += 32) {
            float e = as_[(size_t)g_srcs[k] * H + warp] + ad;
            e = e > 0.f ? e : 0.2f * e;
            ds += __expf(e - m);
        }
#pragma unroll
        for (int o = 16; o; o >>= 1) ds += __shfl_xor_sync(0xffffffffu, ds, o);
        rdn = 1.f / (ds + 1e-16f);
    }

    float4 acc = make_float4(0.f, 0.f, 0.f, 0.f);
    for (int base = s0; base < s1; base += CHUNK) {
        int count = min(CHUNK, s1 - base);
        __syncthreads();
        if (warp < H) {
            for (int j = lane; j < count; j += 32) {
                int s = g_srcs[base + j];
                if (warp == 0) ssrc[j] = s;
                float e = as_[(size_t)s * H + warp] + ad;
                e = e > 0.f ? e : 0.2f * e;
                sw[warp * CHUNK + j] = __expf(e - m) * rdn;
            }
        }
        __syncthreads();
        const float* swh = sw + h * CHUNK;
        for (int j = 0; j < count; j++) {
            float4 f = *(const float4*)(feat + (size_t)ssrc[j] * HC + t4);
            float w = swh[j];
            acc.x = fmaf(f.x, w, acc.x);
            acc.y = fmaf(f.y, w, acc.y);
            acc.z = fmaf(f.z, w, acc.z);
            acc.w = fmaf(f.w, w, acc.w);
        }
    }

    float4 b4 = *(const float4*)(bias + t4);
    float v0 = acc.x + b4.x, v1 = acc.y + b4.y, v2 = acc.z + b4.z, v3 = acc.w + b4.w;
    if (prelu) {
        float a = prelu_a[0];
        v0 = v0 >= 0.f ? v0 : a * v0;
        v1 = v1 >= 0.f ? v1 : a * v1;
        v2 = v2 >= 0.f ? v2 : a * v2;
        v3 = v3 >= 0.f ? v3 : a * v3;
    }
    size_t idx = (size_t)n * HC + t4;
    if (out) {
        *(float4*)(out + idx) = make_float4(v0, v1, v2, v3);
    }
    if (ohi) {
        __nv_bfloat16 h0 = __float2bfloat16(v0);
        __nv_bfloat16 h1 = __float2bfloat16(v1);
        __nv_bfloat16 h2 = __float2bfloat16(v2);
        __nv_bfloat16 h3 = __float2bfloat16(v3);
        __nv_bfloat162 hh01; hh01.x = h0; hh01.y = h1;
        __nv_bfloat162 hh23; hh23.x = h2; hh23.y = h3;
        *(__nv_bfloat162*)(ohi + idx)     = hh01;
        *(__nv_bfloat162*)(ohi + idx + 2) = hh23;
        __nv_bfloat162 ll01;
        ll01.x = __float2bfloat16(v0 - __bfloat162float(h0));
        ll01.y = __float2bfloat16(v1 - __bfloat162float(h1));
        __nv_bfloat162 ll23;
        ll23.x = __float2bfloat16(v2 - __bfloat162float(h2));
        ll23.y = __float2bfloat16(v3 - __bfloat162float(h3));
        *(__nv_bfloat162*)(olo + idx)     = ll01;
        *(__nv_bfloat162*)(olo + idx + 2) = ll23;
    }
}

// ---------------- host orchestration ----------------
static inline int ceil_div(int a, int b) { return (a + b - 1) / b; }

static void run_gemm(const __nv_bfloat16* Ahi, const __nv_bfloat16* Alo,
                     const __nv_bfloat16* Bhi, const __nv_bfloat16* Blo,
                     float* C, int M, int K, int N,
                     const float* asrc, const float* adst,
                     float* as_, float* ad_, int H, int Ch, int a_fp32) {
    dim3 grid(N / 64, ceil_div(M, 128));
    mma_gemm<<<grid, 256>>>(Ahi, Alo, Bhi, Blo, C, M, K, N,
                            asrc, adst, as_, ad_, H, Ch, a_fp32);
}

extern "C" void kernel_launch(void* const* d_in, const int* in_sizes, int n_in,
                              void* d_out, int out_size) {
    const float* x       = (const float*)d_in[0];
    const void*  eidx    = d_in[1];
    const float* W1      = (const float*)d_in[2];
    const float* a_src1  = (const float*)d_in[3];
    const float* a_dst1  = (const float*)d_in[4];
    const float* b1      = (const float*)d_in[5];
    const float* prelu_a = (const float*)d_in[6];
    const float* W2      = (const float*)d_in[7];
    const float* a_src2  = (const float*)d_in[8];
    const float* a_dst2  = (const float*)d_in[9];
    const float* b2      = (const float*)d_in[10];
    const float* Wd      = (const float*)d_in[11];
    const float* a_srcd  = (const float*)d_in[12];
    const float* a_dstd  = (const float*)d_in[13];
    const float* bd      = (const float*)d_in[14];

    const int HHc = in_sizes[3];          // 512
    const int H1  = 4;
    const int C1  = HHc / H1;             // 128
    const int M   = in_sizes[8];          // 256
    const int D   = in_sizes[12];         // 256
    const int N   = in_sizes[0] / D;      // 50000
    const int E   = in_sizes[1] / 2;      // 400000
    const int ET  = E + N;

    float* out   = (float*)d_out;
    float* z     = out;
    float* x_hat = out + (size_t)N * M;

    float *h1, *h2, *hd;
    float *as1, *ad1, *as2, *ad2, *asd, *add;
    __nv_bfloat16 *ahi, *alo, *wthi, *wtlo;
    int *cnt_p;
    cudaGetSymbolAddress((void**)&h1,  g_h1);
    cudaGetSymbolAddress((void**)&h2,  g_h2);
    cudaGetSymbolAddress((void**)&hd,  g_hd);
    cudaGetSymbolAddress((void**)&ahi, g_ahi);
    cudaGetSymbolAddress((void**)&alo, g_alo);
    cudaGetSymbolAddress((void**)&wthi, g_wthi);
    cudaGetSymbolAddress((void**)&wtlo, g_wtlo);
    cudaGetSymbolAddress((void**)&as1, g_as1);
    cudaGetSymbolAddress((void**)&ad1, g_ad1);
    cudaGetSymbolAddress((void**)&as2, g_as2);
    cudaGetSymbolAddress((void**)&ad2, g_ad2);
    cudaGetSymbolAddress((void**)&asd, g_asd);
    cudaGetSymbolAddress((void**)&add, g_add);
    cudaGetSymbolAddress((void**)&cnt_p, g_cnt);

    // ---- layer 1 GEMM (x split fused in-kernel); gemm1 stays 4th launch ----
    wtsplit_kernel<<<ceil_div(D * HHc, 256), 256>>>(W1, wthi, wtlo, D, HHc);
    zero_f2<<<ceil_div(N * H1, 256), 256>>>(as1, ad1, N * H1);
    zero_f2<<<ceil_div(N, 256), 256>>>(as2, ad2, N);
    run_gemm((const __nv_bfloat16*)x, nullptr, wthi, wtlo, h1, N, D, HHc,
             a_src1, a_dst1, as1, ad1, H1, C1, 1);

    // ---- CSR build ----
    build_edges<<<ceil_div(ET, 256), 256>>>(eidx, E, N);
    zero_int<<<ceil_div(N, 256), 256>>>(cnt_p, N);
    hist_kernel<<<ceil_div(ET, 256), 256>>>(ET);
    int nb = ceil_div(N, 1024);
    scan1_kernel<<<nb, 1024>>>(N);
    scan2_kernel<<<1, 64>>>(nb);
    scan3_kernel<<<ceil_div(N, 256), 256>>>(N);
    copy_cursor<<<ceil_div(N, 256), 256>>>(N);
    scatter_kernel<<<ceil_div(ET, 256), 256>>>(ET);

    // ---- layer 1 aggregate (+PReLU, emits split bf16 for next GEMM) ----
    gat_aggregate<<<N, HHc / 4>>>(h1, as1, ad1, b1, nullptr, ahi, alo, H1, C1, 1, prelu_a);

    // ---- layer 2 ----
    wtsplit_kernel<<<ceil_div(HHc * M, 256), 256>>>(W2, wthi, wtlo, HHc, M);
    run_gemm(ahi, alo, wthi, wtlo, h2, N, HHc, M, a_src2, a_dst2, as2, ad2, 1, M, 0);
    zero_f2<<<ceil_div(N, 256), 256>>>(asd, add, N);
    gat_aggregate<<<N, M / 4>>>(h2, as2, ad2, b2, z, ahi, alo, 1, M, 0, prelu_a);

    // ---- decoder ----
    wtsplit_kernel<<<ceil_div(M * D, 256), 256>>>(Wd, wthi, wtlo, M, D);
    run_gemm(ahi, alo, wthi, wtlo, hd, N, M, D, a_srcd, a_dstd, asd, add, 1, D, 0);
    gat_aggregate<<<N, D / 4>>>(hd, asd, add, bd, x_hat, nullptr, nullptr, 1, D, 0, prelu_a);
}